// round 10
// baseline (speedup 1.0000x reference)
#include <cuda_runtime.h>
#include <cuda_bf16.h>
#include <cstdint>

// ---------------------------------------------------------------------------
// BasicBlock (quantized) exact-int8, IMMA convs, cp.async double-buffered.
//   acts int8 NHWC with 1-px halo: [64][34][34][256] (pad pre-filled)
//   weights int8 [O][tap][I]
//   conv = implicit GEMM, block 128 px x 128 oc, warp 32 px x 64 oc,
//          mma.m16n8k32.s8, 2-stage cp.async pipeline.
//   BN stats (+conv1 min/max) fused in conv epilogue.
//   BN1+ReLU+uquant one fused pass; ReLU-max computed analytically.
// ---------------------------------------------------------------------------

#define NPIX   65536          // 64*32*32
#define CCH    256
#define KTOT   2304           // 9*256
#define H2     34             // 32 + halo
#define IMG_W  (H2 * H2 * CCH)      // bytes per image (halo layout)

__device__ __align__(256) int8_t g_a8[64 * IMG_W];        // 18.9 MB halo acts
__device__ __align__(256) float  g_v [NPIX * CCH];        // 67 MB conv out
__device__ __align__(256) int8_t g_w1q[CCH * KTOT];
__device__ __align__(256) int8_t g_w2q[CCH * KTOT];
__device__ int      g_wsum2[CCH];
__device__ unsigned g_maxbits[4];        // |x|max, |w1|max, |w2|max
__device__ float    g_scale[4];          // sx, sw1, sw2, s_unsigned
__device__ float    g_sum[2][CCH], g_sumsq[2][CCH];
__device__ float    g_g[2][CCH], g_b[2][CCH];     // BN affine: g*v + b
__device__ unsigned g_cmin[CCH], g_cmax[CCH];     // conv1 per-channel extremes

// monotone float<->uint encoding (order-preserving for atomicMin/Max)
__device__ __forceinline__ unsigned encf(float f) {
    unsigned b = __float_as_uint(f);
    return (b & 0x80000000u) ? ~b : (b | 0x80000000u);
}
__device__ __forceinline__ float decf(unsigned e) {
    unsigned b = (e & 0x80000000u) ? (e ^ 0x80000000u) : ~e;
    return __uint_as_float(b);
}

#define CP16(dst, src) \
    asm volatile("cp.async.cg.shared.global [%0], [%1], 16;" \
                 :: "r"(dst), "l"(src))

// ------------------------------------------------------------------ init ---
__global__ void k_init() {
    int t = threadIdx.x;
    if (t < 4) g_maxbits[t] = 0u;
    g_sum[0][t] = 0.f; g_sum[1][t] = 0.f;
    g_sumsq[0][t] = 0.f; g_sumsq[1][t] = 0.f;
    g_cmin[t] = 0xffffffffu; g_cmax[t] = 0u;
    g_wsum2[t] = 0;
}

// -------------------------------------------- halo fill (border pixels) ---
// 132 border pixels per image x 64 words. grid = 64 images, 256 threads.
__global__ void k_halo(uint32_t fill) {
    int n = blockIdx.x;
    uint32_t* img = (uint32_t*)(g_a8 + n * IMG_W);
    for (int w = threadIdx.x; w < 132 * 64; w += blockDim.x) {
        int i = w >> 6, part = w & 63;
        int r, c;
        if (i < 34)       { r = 0;        c = i; }
        else if (i < 68)  { r = 33;       c = i - 34; }
        else if (i < 100) { r = i - 67;   c = 0; }    // rows 1..32
        else              { r = i - 99;   c = 33; }   // rows 1..32
        img[(r * H2 + c) * 64 + part] = fill;
    }
}

// ------------------------------------------------------- max |.| reduce ---
__global__ void k_maxabs4(const float4* __restrict__ p, int n4, int slot) {
    float m = 0.f;
    for (int i = blockIdx.x * blockDim.x + threadIdx.x; i < n4;
         i += gridDim.x * blockDim.x) {
        float4 v = p[i];
        m = fmaxf(m, fmaxf(fmaxf(fabsf(v.x), fabsf(v.y)),
                           fmaxf(fabsf(v.z), fabsf(v.w))));
    }
    #pragma unroll
    for (int o = 16; o; o >>= 1) m = fmaxf(m, __shfl_xor_sync(~0u, m, o));
    if ((threadIdx.x & 31) == 0)
        atomicMax(&g_maxbits[slot], __float_as_uint(m));  // nonneg float bits
}

__global__ void k_scales() {
    g_scale[0] = __uint_as_float(g_maxbits[0]) / 127.f + 1e-12f;
    g_scale[1] = __uint_as_float(g_maxbits[1]) / 127.f + 1e-12f;
    g_scale[2] = __uint_as_float(g_maxbits[2]) / 127.f + 1e-12f;
}

// ------------------------- quantize x: NCHW -> halo NHWC s8 (interior) ---
__global__ void k_quant_x(const float* __restrict__ x) {
    __shared__ uint32_t tile32[32 * 66];
    int8_t* tile = (int8_t*)tile32;
    int n = blockIdx.x >> 5;
    int r = blockIdx.x & 31;          // one full image row per block
    int hw0 = r * 32;
    int tid = threadIdx.x;
    float s = g_scale[0];
    for (int j = 0; j < 32; ++j) {
        int idx = j * 256 + tid;
        int c   = idx >> 5;
        int pix = idx & 31;
        float v = x[((n * 256 + c) << 10) + hw0 + pix];
        float q = fminf(fmaxf(rintf(v / s), -128.f), 127.f);
        tile[pix * 264 + c] = (int8_t)q;
    }
    __syncthreads();
    uint32_t* dst = (uint32_t*)(g_a8 + n * IMG_W) + ((r + 1) * H2 + 1) * 64;
    for (int j = 0; j < 8; ++j) {
        int w   = j * 256 + tid;
        int pix = w >> 6;
        int cw  = w & 63;
        dst[pix * 64 + cw] = *(const uint32_t*)(tile + pix * 264 + cw * 4);
    }
}

// -------------------------------- quantize weights: OIHW -> [O][t][I] s8 ---
__global__ void k_quant_w(const float* __restrict__ w, int which) {
    int8_t* wq = which ? g_w2q : g_w1q;
    float s = g_scale[which ? 2 : 1];
    for (int idx = blockIdx.x * blockDim.x + threadIdx.x; idx < CCH * KTOT;
         idx += gridDim.x * blockDim.x) {
        int i = idx & 255;
        int t = (idx >> 8) % 9;
        int o = idx / KTOT;
        float v = w[(o * 256 + i) * 9 + t];
        float q = fminf(fmaxf(rintf(v / s), -128.f), 127.f);
        wq[idx] = (int8_t)q;
    }
}

// per-out-channel sum of quantized w2 (unsigned zero-point trick)
__global__ void k_wsum() {
    int o = blockIdx.x, tid = threadIdx.x;
    int s = 0;
    #pragma unroll
    for (int t = 0; t < 9; ++t) s += (int)g_w2q[(o * 9 + t) * 256 + tid];
    #pragma unroll
    for (int off = 16; off; off >>= 1) s += __shfl_xor_sync(~0u, s, off);
    __shared__ int ws[8];
    if ((tid & 31) == 0) ws[tid >> 5] = s;
    __syncthreads();
    if (tid == 0) {
        int tot = 0;
        #pragma unroll
        for (int i = 0; i < 8; ++i) tot += ws[i];
        g_wsum2[o] = tot;
    }
}

// ------------------------------------------- conv3x3 as int8 IMMA GEMM ----
// grid = (512 pixel-tiles, 2 oc-tiles). Block tile = 128 px x 128 oc.
// 8 warps: (w&3) -> 32-px m-slice, (w>>2) -> 64-oc n-slice.
// 2-stage cp.async pipeline over 36 K-chunks (9 taps x 4 ic-chunks of 64B).
// SMEM stride 20 words (80 B): conflict-free ldmatrix phases.
template <bool UNSIGNED>
__global__ void __launch_bounds__(256, 2)
k_conv(int which) {
    // [buf][A=0/B=1][128 rows * 20 words]  = 40 KB static
    __shared__ __align__(16) uint32_t smemT[2][2][2560];
    const int8_t* Wq = which ? g_w2q : g_w1q;
    constexpr int STAGE = UNSIGNED ? 1 : 0;
    const int BUFB = 2 * 2560 * 4;            // bytes per pipeline stage

    int ptile = blockIdx.x;                   // 0..511
    int n  = ptile >> 3;
    int r4 = ptile & 7;                       // 4-row group
    int obase = blockIdx.y * 128;
    int tid = threadIdx.x;
    int warp = tid >> 5, lane = tid & 31;
    int m0 = (warp & 3) * 32;                 // pixel slice (32 px)
    int n0 = (warp >> 2) * 64;                // oc slice (64 oc)

    uint32_t smemBase = (uint32_t)__cvta_generic_to_shared(&smemT[0][0][0]);

    // ---- staging: thread = (spix 0..63, w0 0..3), per ph copies 16B ----
    int spix = tid >> 2;
    int w0   = tid & 3;
    const int8_t* srcA0[2];                   // per-ph A base (halo, tap 0,0)
    const int8_t* srcB0[2];
    uint32_t dstA[2], dstB[2];
    #pragma unroll
    for (int ph = 0; ph < 2; ++ph) {
        int p128 = ph * 64 + spix;
        int r_im = r4 * 4 + (p128 >> 5);
        int c_im = p128 & 31;
        srcA0[ph] = g_a8 + (size_t)n * IMG_W
                  + ((r_im + 1) * H2 + (c_im + 1)) * 256 + w0 * 16;
        srcB0[ph] = Wq + (size_t)(obase + p128) * KTOT + w0 * 16;
        dstA[ph] = smemBase + (p128 * 20 + w0 * 4) * 4;             // A region
        dstB[ph] = smemBase + 10240 + (p128 * 20 + w0 * 4) * 4;     // B region
    }

    // ---- ldmatrix fragment addresses (relative; add buf*BUFB) ----
    uint32_t aAddr[2][2], bAddr0[4];
    #pragma unroll
    for (int mf = 0; mf < 2; ++mf)
        #pragma unroll
        for (int s = 0; s < 2; ++s)
            aAddr[mf][s] = smemBase + (m0 + mf * 16 + (lane & 15)) * 80
                         + (lane >> 4) * 16 + s * 32;
    #pragma unroll
    for (int j = 0; j < 4; ++j)
        bAddr0[j] = smemBase + 10240 + (n0 + j * 8 + (lane & 7)) * 80
                  + (lane >> 3) * 16;

    int acc[2][8][4] = {};

    // issue one 64B ic-chunk of one tap into stage `buf`
    auto issue = [&](int q, int buf) {
        int t = q >> 2, kc = q & 3;
        int tapoff = ((t / 3 - 1) * H2 + (t % 3 - 1)) * 256 + kc * 64;
        int boff = q * 64;                    // (t*256 + kc*64)
        uint32_t bo = (uint32_t)buf * BUFB;
        #pragma unroll
        for (int ph = 0; ph < 2; ++ph) {
            CP16(dstA[ph] + bo, srcA0[ph] + tapoff);
            CP16(dstB[ph] + bo, srcB0[ph] + boff);
        }
        asm volatile("cp.async.commit_group;");
    };

    issue(0, 0);
    for (int q = 0; q < 36; ++q) {
        int buf = q & 1;
        if (q < 35) {
            issue(q + 1, buf ^ 1);
            asm volatile("cp.async.wait_group 1;");
        } else {
            asm volatile("cp.async.wait_group 0;");
        }
        __syncthreads();

        uint32_t bo = (uint32_t)buf * BUFB;
        uint32_t a[2][2][4];
        #pragma unroll
        for (int mf = 0; mf < 2; ++mf)
            #pragma unroll
            for (int s = 0; s < 2; ++s)
                asm volatile(
                    "ldmatrix.sync.aligned.m8n8.x4.shared.b16 {%0,%1,%2,%3}, [%4];"
                    : "=r"(a[mf][s][0]), "=r"(a[mf][s][1]),
                      "=r"(a[mf][s][2]), "=r"(a[mf][s][3])
                    : "r"(aAddr[mf][s] + bo));
        #pragma unroll
        for (int nh = 0; nh < 2; ++nh) {
            uint32_t b[4][4];
            #pragma unroll
            for (int j = 0; j < 4; ++j)
                asm volatile(
                    "ldmatrix.sync.aligned.m8n8.x4.shared.b16 {%0,%1,%2,%3}, [%4];"
                    : "=r"(b[j][0]), "=r"(b[j][1]), "=r"(b[j][2]), "=r"(b[j][3])
                    : "r"(bAddr0[j] + nh * 2560 + bo));
            #pragma unroll
            for (int mf = 0; mf < 2; ++mf)
                #pragma unroll
                for (int j = 0; j < 4; ++j)
                    #pragma unroll
                    for (int s = 0; s < 2; ++s)
                        asm volatile(
                            "mma.sync.aligned.m16n8k32.row.col.s32.s8.s8.s32 "
                            "{%0,%1,%2,%3}, {%4,%5,%6,%7}, {%8,%9}, {%0,%1,%2,%3};"
                            : "+r"(acc[mf][nh * 4 + j][0]),
                              "+r"(acc[mf][nh * 4 + j][1]),
                              "+r"(acc[mf][nh * 4 + j][2]),
                              "+r"(acc[mf][nh * 4 + j][3])
                            : "r"(a[mf][s][0]), "r"(a[mf][s][1]),
                              "r"(a[mf][s][2]), "r"(a[mf][s][3]),
                              "r"(b[j][2 * s]), "r"(b[j][2 * s + 1]));
        }
        __syncthreads();                      // protect buf before reuse
    }

    // ------------------------------ epilogue: write f32 + fused BN stats ---
    float s = UNSIGNED ? g_scale[3] * g_scale[2] : g_scale[0] * g_scale[1];
    int groupID = lane >> 2, tig = lane & 3;

    #pragma unroll
    for (int j8 = 0; j8 < 8; ++j8) {
        int oc = obase + n0 + j8 * 8 + tig * 2;
        int wsa = 0, wsb = 0;
        if (UNSIGNED) { wsa = 128 * g_wsum2[oc]; wsb = 128 * g_wsum2[oc + 1]; }
        float sx = 0.f, sy = 0.f, qx = 0.f, qy = 0.f;
        float mnx = 1e30f, mxx = -1e30f, mny = 1e30f, mxy = -1e30f;
        #pragma unroll
        for (int mf = 0; mf < 2; ++mf) {
            int pix0 = m0 + mf * 16 + groupID;        // tile-local 0..127
            #pragma unroll
            for (int half = 0; half < 2; ++half) {
                int pix = pix0 + half * 8;
                int gp = n * 1024 + (r4 * 4 + (pix >> 5)) * 32 + (pix & 31);
                int c0 = acc[mf][j8][half * 2]     + wsa;
                int c1 = acc[mf][j8][half * 2 + 1] + wsb;
                float va = s * (float)c0, vb = s * (float)c1;
                *(float2*)(g_v + gp * 256 + oc) = make_float2(va, vb);
                sx += va; sy += vb;
                qx += va * va; qy += vb * vb;
                if (!UNSIGNED) {
                    mnx = fminf(mnx, va); mxx = fmaxf(mxx, va);
                    mny = fminf(mny, vb); mxy = fmaxf(mxy, vb);
                }
            }
        }
        #pragma unroll
        for (int o = 4; o < 32; o <<= 1) {    // reduce across the 8 groupIDs
            sx += __shfl_xor_sync(~0u, sx, o);
            sy += __shfl_xor_sync(~0u, sy, o);
            qx += __shfl_xor_sync(~0u, qx, o);
            qy += __shfl_xor_sync(~0u, qy, o);
            if (!UNSIGNED) {
                mnx = fminf(mnx, __shfl_xor_sync(~0u, mnx, o));
                mxx = fmaxf(mxx, __shfl_xor_sync(~0u, mxx, o));
                mny = fminf(mny, __shfl_xor_sync(~0u, mny, o));
                mxy = fmaxf(mxy, __shfl_xor_sync(~0u, mxy, o));
            }
        }
        if (groupID == 0) {
            atomicAdd(&g_sum[STAGE][oc],       sx);
            atomicAdd(&g_sum[STAGE][oc + 1],   sy);
            atomicAdd(&g_sumsq[STAGE][oc],     qx);
            atomicAdd(&g_sumsq[STAGE][oc + 1], qy);
            if (!UNSIGNED) {
                atomicMin(&g_cmin[oc],     encf(mnx));
                atomicMax(&g_cmax[oc],     encf(mxx));
                atomicMin(&g_cmin[oc + 1], encf(mny));
                atomicMax(&g_cmax[oc + 1], encf(mxy));
            }
        }
    }
}

// -------- finalize BN1: affine coeffs + analytic ReLU-max -> u8 scale ----
__global__ void k_finalize1(const float* __restrict__ gamma,
                            const float* __restrict__ beta) {
    int c = threadIdx.x;
    float m   = g_sum[0][c] * (1.f / 65536.f);
    float var = g_sumsq[0][c] * (1.f / 65536.f) - m * m;
    float rstd = 1.f / sqrtf(var + 1e-5f);
    float g1 = gamma[c] * rstd;
    float b1 = beta[c] - m * g1;
    g_g[0][c] = g1; g_b[0][c] = b1;
    float cmax = decf(g_cmax[c]), cmin = decf(g_cmin[c]);
    float hi = fmaxf(fmaxf(g1 * cmax + b1, g1 * cmin + b1), 0.f);
    __shared__ float red[256];
    red[c] = hi; __syncthreads();
    #pragma unroll
    for (int o = 128; o; o >>= 1) {
        if (c < o) red[c] = fmaxf(red[c], red[c + o]);
        __syncthreads();
    }
    if (c == 0) g_scale[3] = red[0] / 255.f + 1e-12f;
}

__global__ void k_finalize2(const float* __restrict__ gamma,
                            const float* __restrict__ beta) {
    int c = threadIdx.x;
    float m   = g_sum[1][c] * (1.f / 65536.f);
    float var = g_sumsq[1][c] * (1.f / 65536.f) - m * m;
    float rstd = 1.f / sqrtf(var + 1e-5f);
    float g2 = gamma[c] * rstd;
    g_g[1][c] = g2;
    g_b[1][c] = beta[c] - m * g2;
}

// ------ fused BN1 + ReLU + unsigned quant -> halo buffer (u-128 as s8) ----
__global__ void k_bn_quant() {
    __shared__ float sg[256], sb[256];
    if (threadIdx.x < 256) {
        sg[threadIdx.x] = g_g[0][threadIdx.x];
        sb[threadIdx.x] = g_b[0][threadIdx.x];
    }
    __syncthreads();
    float s = g_scale[3];
    int stride = gridDim.x * blockDim.x;
    for (int w = blockIdx.x * blockDim.x + threadIdx.x; w < NPIX * 64;
         w += stride) {
        float4 vv = ((const float4*)g_v)[w];
        int c = (w * 4) & 255;
        float r0 = fmaxf(sg[c]     * vv.x + sb[c],     0.f);
        float r1 = fmaxf(sg[c + 1] * vv.y + sb[c + 1], 0.f);
        float r2 = fmaxf(sg[c + 2] * vv.z + sb[c + 2], 0.f);
        float r3 = fmaxf(sg[c + 3] * vv.w + sb[c + 3], 0.f);
        int q0 = (int)fminf(fmaxf(rintf(r0 / s), 0.f), 255.f) - 128;
        int q1 = (int)fminf(fmaxf(rintf(r1 / s), 0.f), 255.f) - 128;
        int q2 = (int)fminf(fmaxf(rintf(r2 / s), 0.f), 255.f) - 128;
        int q3 = (int)fminf(fmaxf(rintf(r3 / s), 0.f), 255.f) - 128;
        uint32_t pk = (uint32_t)(q0 & 255) | ((uint32_t)(q1 & 255) << 8) |
                      ((uint32_t)(q2 & 255) << 16) | ((uint32_t)(q3 & 255) << 24);
        // halo layout dst
        int p  = w >> 6, cw = w & 63;
        int nn = p >> 10, rc = p & 1023;
        int r  = rc >> 5, cc = rc & 31;
        ((uint32_t*)(g_a8 + (size_t)nn * IMG_W))
            [((r + 1) * H2 + (cc + 1)) * 64 + cw] = pk;
    }
}

// ----------------- BN2 + residual + ReLU, NHWC -> NCHW transpose, write ---
__global__ void k_final(const float* __restrict__ x, float* __restrict__ out) {
    __shared__ float tile[32 * 257];
    int n   = blockIdx.x >> 5;
    int hw0 = (blockIdx.x & 31) * 32;
    int tid = threadIdx.x;
    float g2 = g_g[1][tid], b2 = g_b[1][tid];
    const float* v = g_v + (n * 1024 + hw0) * 256;
    for (int j = 0; j < 32; ++j)
        tile[j * 257 + tid] = g2 * v[j * 256 + tid] + b2;
    __syncthreads();
    for (int j = 0; j < 32; ++j) {
        int idx = j * 256 + tid;
        int c   = idx >> 5;
        int pix = idx & 31;
        int gi = ((n * 256 + c) << 10) + hw0 + pix;
        float r = tile[pix * 257 + c] + x[gi];
        out[gi] = fmaxf(r, 0.f);
    }
}

// ---------------------------------------------------------------------------
extern "C" void kernel_launch(void* const* d_in, const int* in_sizes, int n_in,
                              void* d_out, int out_size) {
    const float* x      = (const float*)d_in[0];
    const float* w1     = (const float*)d_in[1];
    const float* gamma1 = (const float*)d_in[2];
    const float* beta1  = (const float*)d_in[3];
    const float* w2     = (const float*)d_in[4];
    const float* gamma2 = (const float*)d_in[5];
    const float* beta2  = (const float*)d_in[6];
    float* out = (float*)d_out;

    k_init<<<1, 256>>>();
    k_maxabs4<<<1184, 256>>>((const float4*)x,  NPIX * 64, 0);
    k_maxabs4<<<64, 256>>>((const float4*)w1, CCH * KTOT / 4, 1);
    k_maxabs4<<<64, 256>>>((const float4*)w2, CCH * KTOT / 4, 2);
    k_scales<<<1, 1>>>();

    k_halo<<<64, 256>>>(0u);                 // conv1 pad = signed 0
    k_quant_x<<<2048, 256>>>(x);
    k_quant_w<<<512, 256>>>(w1, 0);
    k_quant_w<<<512, 256>>>(w2, 1);
    k_wsum<<<256, 256>>>();

    dim3 cgrid(512, 2);
    k_conv<false><<<cgrid, 256>>>(0);        // conv1 + BN1 stats + min/max
    k_finalize1<<<1, 256>>>(gamma1, beta1);  // affine + analytic relu-max
    k_halo<<<64, 256>>>(0x80808080u);        // conv2 pad = u0 (-128)
    k_bn_quant<<<4096, 256>>>();             // BN1+ReLU+uquant, one pass

    k_conv<true><<<cgrid, 256>>>(1);         // conv2 + BN2 stats
    k_finalize2<<<1, 256>>>(gamma2, beta2);
    k_final<<<2048, 256>>>(x, out);          // BN2 + residual + ReLU -> NCHW
}

// round 15
// speedup vs baseline: 1.0229x; 1.0229x over previous
#include <cuda_runtime.h>
#include <cuda_bf16.h>
#include <cstdint>

// ---------------------------------------------------------------------------
// BasicBlock (quantized) exact-int8, IMMA convs, cp.async double-buffered.
//   acts int8 NHWC with 1-px halo: [64][34][34][256] (pad pre-filled)
//   conv = implicit GEMM, block 128 px x 128 oc, warp 32 px x 64 oc,
//          mma.m16n8k32.s8, 2-stage cp.async pipeline.
//   Launch order arranged so conv1 is ncu ordinal 5 (-s 5 -c 1).
//   launch_bounds WITHOUT minBlocks: never spill (spills were prime suspect
//   for the 8x conv slowdown at 1249 us).
// ---------------------------------------------------------------------------

#define NPIX   65536          // 64*32*32
#define CCH    256
#define KTOT   2304           // 9*256
#define H2     34             // 32 + halo
#define IMG_W  (H2 * H2 * CCH)      // bytes per image (halo layout)

__device__ __align__(256) int8_t g_a8[64 * IMG_W];        // 18.9 MB halo acts
__device__ __align__(256) float  g_v [NPIX * CCH];        // 67 MB conv out
__device__ __align__(256) int8_t g_w1q[CCH * KTOT];
__device__ __align__(256) int8_t g_w2q[CCH * KTOT];
__device__ int      g_wsum2[CCH];
__device__ unsigned g_maxbits[4];        // |x|max, |w1|max, |w2|max
__device__ float    g_scale[4];          // [3] = unsigned act scale
__device__ float    g_sum[2][CCH], g_sumsq[2][CCH];
__device__ float    g_g[2][CCH], g_b[2][CCH];     // BN affine: g*v + b
__device__ unsigned g_cmin[CCH], g_cmax[CCH];     // conv1 per-channel extremes

// scale from raw nonneg float bits in g_maxbits (identical math everywhere)
__device__ __forceinline__ float mscale(int slot) {
    return __uint_as_float(g_maxbits[slot]) / 127.f + 1e-12f;
}

// monotone float<->uint encoding (order-preserving for atomicMin/Max)
__device__ __forceinline__ unsigned encf(float f) {
    unsigned b = __float_as_uint(f);
    return (b & 0x80000000u) ? ~b : (b | 0x80000000u);
}
__device__ __forceinline__ float decf(unsigned e) {
    unsigned b = (e & 0x80000000u) ? (e ^ 0x80000000u) : ~e;
    return __uint_as_float(b);
}

#define CP16(dst, src) \
    asm volatile("cp.async.cg.shared.global [%0], [%1], 16;" \
                 :: "r"(dst), "l"(src))

// --------------------------- init scalars + conv1 halo fill (one launch) ---
__global__ void k_init_halo() {
    int n = blockIdx.x;
    int tid = threadIdx.x;
    if (n == 0) {
        if (tid < 4) g_maxbits[tid] = 0u;
        g_sum[0][tid] = 0.f; g_sum[1][tid] = 0.f;
        g_sumsq[0][tid] = 0.f; g_sumsq[1][tid] = 0.f;
        g_cmin[tid] = 0xffffffffu; g_cmax[tid] = 0u;
        g_wsum2[tid] = 0;
    }
    uint32_t* img = (uint32_t*)(g_a8 + n * IMG_W);
    for (int w = tid; w < 132 * 64; w += blockDim.x) {
        int i = w >> 6, part = w & 63;
        int r, c;
        if (i < 34)       { r = 0;        c = i; }
        else if (i < 68)  { r = 33;       c = i - 34; }
        else if (i < 100) { r = i - 67;   c = 0; }    // rows 1..32
        else              { r = i - 99;   c = 33; }   // rows 1..32
        img[(r * H2 + c) * 64 + part] = 0u;
    }
}

// -------------------------------------------- halo fill (conv2, pad=0x80) ---
__global__ void k_halo2() {
    int n = blockIdx.x;
    uint32_t* img = (uint32_t*)(g_a8 + n * IMG_W);
    for (int w = threadIdx.x; w < 132 * 64; w += blockDim.x) {
        int i = w >> 6, part = w & 63;
        int r, c;
        if (i < 34)       { r = 0;        c = i; }
        else if (i < 68)  { r = 33;       c = i - 34; }
        else if (i < 100) { r = i - 67;   c = 0; }
        else              { r = i - 99;   c = 33; }
        img[(r * H2 + c) * 64 + part] = 0x80808080u;
    }
}

// ------------------------------- all three max|.| reductions, one launch ---
__global__ void k_maxabs_all(const float4* __restrict__ x,
                             const float4* __restrict__ w1,
                             const float4* __restrict__ w2) {
    int b = blockIdx.x;
    const float4* p; int n4, slot, b0, nb;
    if (b < 1184)      { p = x;  n4 = NPIX * 64;      slot = 0; b0 = b;        nb = 1184; }
    else if (b < 1248) { p = w1; n4 = CCH * KTOT / 4; slot = 1; b0 = b - 1184; nb = 64; }
    else               { p = w2; n4 = CCH * KTOT / 4; slot = 2; b0 = b - 1248; nb = 64; }
    float m = 0.f;
    for (int i = b0 * blockDim.x + threadIdx.x; i < n4; i += nb * blockDim.x) {
        float4 v = p[i];
        m = fmaxf(m, fmaxf(fmaxf(fabsf(v.x), fabsf(v.y)),
                           fmaxf(fabsf(v.z), fabsf(v.w))));
    }
    #pragma unroll
    for (int o = 16; o; o >>= 1) m = fmaxf(m, __shfl_xor_sync(~0u, m, o));
    if ((threadIdx.x & 31) == 0)
        atomicMax(&g_maxbits[slot], __float_as_uint(m));  // nonneg float bits
}

// ------------------------- quantize x: NCHW -> halo NHWC s8 (interior) ---
__global__ void k_quant_x(const float* __restrict__ x) {
    __shared__ uint32_t tile32[32 * 66];
    int8_t* tile = (int8_t*)tile32;
    int n = blockIdx.x >> 5;
    int r = blockIdx.x & 31;          // one full image row per block
    int hw0 = r * 32;
    int tid = threadIdx.x;
    float s = mscale(0);
    for (int j = 0; j < 32; ++j) {
        int idx = j * 256 + tid;
        int c   = idx >> 5;
        int pix = idx & 31;
        float v = x[((n * 256 + c) << 10) + hw0 + pix];
        float q = fminf(fmaxf(rintf(v / s), -128.f), 127.f);
        tile[pix * 264 + c] = (int8_t)q;
    }
    __syncthreads();
    uint32_t* dst = (uint32_t*)(g_a8 + n * IMG_W) + ((r + 1) * H2 + 1) * 64;
    for (int j = 0; j < 8; ++j) {
        int w   = j * 256 + tid;
        int pix = w >> 6;
        int cw  = w & 63;
        dst[pix * 64 + cw] = *(const uint32_t*)(tile + pix * 264 + cw * 4);
    }
}

// --------------------- quantize BOTH weights: OIHW -> [O][t][I] s8 --------
__global__ void k_quant_w_both(const float* __restrict__ w1,
                               const float* __restrict__ w2) {
    int which = blockIdx.x >= 512;
    const float* w = which ? w2 : w1;
    int8_t* wq = which ? g_w2q : g_w1q;
    float s = mscale(which ? 2 : 1);
    int b0 = blockIdx.x & 511;
    for (int idx = b0 * blockDim.x + threadIdx.x; idx < CCH * KTOT;
         idx += 512 * blockDim.x) {
        int i = idx & 255;
        int t = (idx >> 8) % 9;
        int o = idx / KTOT;
        float v = w[(o * 256 + i) * 9 + t];
        float q = fminf(fmaxf(rintf(v / s), -128.f), 127.f);
        wq[idx] = (int8_t)q;
    }
}

// per-out-channel sum of quantized w2 (unsigned zero-point trick)
__global__ void k_wsum() {
    int o = blockIdx.x, tid = threadIdx.x;
    int s = 0;
    #pragma unroll
    for (int t = 0; t < 9; ++t) s += (int)g_w2q[(o * 9 + t) * 256 + tid];
    #pragma unroll
    for (int off = 16; off; off >>= 1) s += __shfl_xor_sync(~0u, s, off);
    __shared__ int ws[8];
    if ((tid & 31) == 0) ws[tid >> 5] = s;
    __syncthreads();
    if (tid == 0) {
        int tot = 0;
        #pragma unroll
        for (int i = 0; i < 8; ++i) tot += ws[i];
        g_wsum2[o] = tot;
    }
}

// ------------------------------------------- conv3x3 as int8 IMMA GEMM ----
// grid = (512 pixel-tiles, 2 oc-tiles). Block tile = 128 px x 128 oc.
// 8 warps: (w&3) -> 32-px m-slice, (w>>2) -> 64-oc n-slice.
// 2-stage cp.async pipeline over 36 K-chunks (9 taps x 4 ic-chunks of 64B).
// launch_bounds without minBlocks: ptxas must not spill (reg cap = 255).
template <bool UNSIGNED>
__global__ void __launch_bounds__(256)
k_conv(int which) {
    // [buf][A=0/B=1][128 rows * 20 words]  = 40 KB static
    __shared__ __align__(16) uint32_t smemT[2][2][2560];
    const int8_t* Wq = which ? g_w2q : g_w1q;
    constexpr int STAGE = UNSIGNED ? 1 : 0;
    const int BUFB = 2 * 2560 * 4;            // bytes per pipeline stage

    int ptile = blockIdx.x;                   // 0..511
    int n  = ptile >> 3;
    int r4 = ptile & 7;                       // 4-row group
    int obase = blockIdx.y * 128;
    int tid = threadIdx.x;
    int warp = tid >> 5, lane = tid & 31;
    int m0 = (warp & 3) * 32;                 // pixel slice (32 px)
    int n0 = (warp >> 2) * 64;                // oc slice (64 oc)

    uint32_t smemBase = (uint32_t)__cvta_generic_to_shared(&smemT[0][0][0]);

    // ---- staging: thread = (spix 0..63, w0 0..3); ph=1 via const offsets --
    int spix = tid >> 2;
    int w0   = tid & 3;
    const int8_t* srcA = g_a8 + (size_t)n * IMG_W
                       + ((r4 * 4 + (spix >> 5) + 1) * H2 + (spix & 31) + 1) * 256
                       + w0 * 16;             // ph=1: +2 rows = +17408 B
    const int8_t* srcB = Wq + (size_t)(obase + spix) * KTOT + w0 * 16;  // ph=1: +64*KTOT
    uint32_t dstA0 = smemBase + (spix * 20 + w0 * 4) * 4;           // ph=1: +5120
    uint32_t dstB0 = smemBase + 10240 + (spix * 20 + w0 * 4) * 4;   // ph=1: +5120

    // ---- ldmatrix fragment addresses (relative; add buf*BUFB) ----
    uint32_t aAddr[2][2], bAddr0[4];
    #pragma unroll
    for (int mf = 0; mf < 2; ++mf)
        #pragma unroll
        for (int s = 0; s < 2; ++s)
            aAddr[mf][s] = smemBase + (m0 + mf * 16 + (lane & 15)) * 80
                         + (lane >> 4) * 16 + s * 32;
    #pragma unroll
    for (int j = 0; j < 4; ++j)
        bAddr0[j] = smemBase + 10240 + (n0 + j * 8 + (lane & 7)) * 80
                  + (lane >> 3) * 16;

    int acc[2][8][4] = {};

    // issue one 64B ic-chunk of one tap into stage `buf`
    auto issue = [&](int q, int buf) {
        int t = q >> 2, kc = q & 3;
        int tapoff = ((t / 3 - 1) * H2 + (t % 3 - 1)) * 256 + kc * 64;
        int boff = q * 64;                    // (t*256 + kc*64)
        uint32_t bo = (uint32_t)buf * BUFB;
        CP16(dstA0 + bo,        srcA + tapoff);
        CP16(dstB0 + bo,        srcB + boff);
        CP16(dstA0 + bo + 5120, srcA + tapoff + 2 * H2 * 256);
        CP16(dstB0 + bo + 5120, srcB + boff + 64 * KTOT);
        asm volatile("cp.async.commit_group;");
    };

    issue(0, 0);
    for (int q = 0; q < 36; ++q) {
        int buf = q & 1;
        if (q < 35) {
            issue(q + 1, buf ^ 1);
            asm volatile("cp.async.wait_group 1;");
        } else {
            asm volatile("cp.async.wait_group 0;");
        }
        __syncthreads();

        uint32_t bo = (uint32_t)buf * BUFB;
        uint32_t a[2][2][4];
        #pragma unroll
        for (int mf = 0; mf < 2; ++mf)
            #pragma unroll
            for (int s = 0; s < 2; ++s)
                asm volatile(
                    "ldmatrix.sync.aligned.m8n8.x4.shared.b16 {%0,%1,%2,%3}, [%4];"
                    : "=r"(a[mf][s][0]), "=r"(a[mf][s][1]),
                      "=r"(a[mf][s][2]), "=r"(a[mf][s][3])
                    : "r"(aAddr[mf][s] + bo));
        #pragma unroll
        for (int nh = 0; nh < 2; ++nh) {
            uint32_t b[4][4];
            #pragma unroll
            for (int j = 0; j < 4; ++j)
                asm volatile(
                    "ldmatrix.sync.aligned.m8n8.x4.shared.b16 {%0,%1,%2,%3}, [%4];"
                    : "=r"(b[j][0]), "=r"(b[j][1]), "=r"(b[j][2]), "=r"(b[j][3])
                    : "r"(bAddr0[j] + nh * 2560 + bo));
            #pragma unroll
            for (int mf = 0; mf < 2; ++mf)
                #pragma unroll
                for (int j = 0; j < 4; ++j)
                    #pragma unroll
                    for (int s = 0; s < 2; ++s)
                        asm volatile(
                            "mma.sync.aligned.m16n8k32.row.col.s32.s8.s8.s32 "
                            "{%0,%1,%2,%3}, {%4,%5,%6,%7}, {%8,%9}, {%0,%1,%2,%3};"
                            : "+r"(acc[mf][nh * 4 + j][0]),
                              "+r"(acc[mf][nh * 4 + j][1]),
                              "+r"(acc[mf][nh * 4 + j][2]),
                              "+r"(acc[mf][nh * 4 + j][3])
                            : "r"(a[mf][s][0]), "r"(a[mf][s][1]),
                              "r"(a[mf][s][2]), "r"(a[mf][s][3]),
                              "r"(b[j][2 * s]), "r"(b[j][2 * s + 1]));
        }
        __syncthreads();                      // protect buf before reuse
    }

    // ------------------------------ epilogue: write f32 + fused BN stats ---
    float s = UNSIGNED ? g_scale[3] * mscale(2) : mscale(0) * mscale(1);
    int groupID = lane >> 2, tig = lane & 3;

    #pragma unroll
    for (int j8 = 0; j8 < 8; ++j8) {
        int oc = obase + n0 + j8 * 8 + tig * 2;
        int wsa = 0, wsb = 0;
        if (UNSIGNED) { wsa = 128 * g_wsum2[oc]; wsb = 128 * g_wsum2[oc + 1]; }
        float sx = 0.f, sy = 0.f, qx = 0.f, qy = 0.f;
        float mnx = 1e30f, mxx = -1e30f, mny = 1e30f, mxy = -1e30f;
        #pragma unroll
        for (int mf = 0; mf < 2; ++mf) {
            int pix0 = m0 + mf * 16 + groupID;        // tile-local 0..127
            #pragma unroll
            for (int half = 0; half < 2; ++half) {
                int pix = pix0 + half * 8;
                int gp = n * 1024 + (r4 * 4 + (pix >> 5)) * 32 + (pix & 31);
                int c0 = acc[mf][j8][half * 2]     + wsa;
                int c1 = acc[mf][j8][half * 2 + 1] + wsb;
                float va = s * (float)c0, vb = s * (float)c1;
                *(float2*)(g_v + gp * 256 + oc) = make_float2(va, vb);
                sx += va; sy += vb;
                qx += va * va; qy += vb * vb;
                if (!UNSIGNED) {
                    mnx = fminf(mnx, va); mxx = fmaxf(mxx, va);
                    mny = fminf(mny, vb); mxy = fmaxf(mxy, vb);
                }
            }
        }
        #pragma unroll
        for (int o = 4; o < 32; o <<= 1) {    // reduce across the 8 groupIDs
            sx += __shfl_xor_sync(~0u, sx, o);
            sy += __shfl_xor_sync(~0u, sy, o);
            qx += __shfl_xor_sync(~0u, qx, o);
            qy += __shfl_xor_sync(~0u, qy, o);
            if (!UNSIGNED) {
                mnx = fminf(mnx, __shfl_xor_sync(~0u, mnx, o));
                mxx = fmaxf(mxx, __shfl_xor_sync(~0u, mxx, o));
                mny = fminf(mny, __shfl_xor_sync(~0u, mny, o));
                mxy = fmaxf(mxy, __shfl_xor_sync(~0u, mxy, o));
            }
        }
        if (groupID == 0) {
            atomicAdd(&g_sum[STAGE][oc],       sx);
            atomicAdd(&g_sum[STAGE][oc + 1],   sy);
            atomicAdd(&g_sumsq[STAGE][oc],     qx);
            atomicAdd(&g_sumsq[STAGE][oc + 1], qy);
            if (!UNSIGNED) {
                atomicMin(&g_cmin[oc],     encf(mnx));
                atomicMax(&g_cmax[oc],     encf(mxx));
                atomicMin(&g_cmin[oc + 1], encf(mny));
                atomicMax(&g_cmax[oc + 1], encf(mxy));
            }
        }
    }
}

// -------- finalize BN1: affine coeffs + analytic ReLU-max -> u8 scale ----
__global__ void k_finalize1(const float* __restrict__ gamma,
                            const float* __restrict__ beta) {
    int c = threadIdx.x;
    float m   = g_sum[0][c] * (1.f / 65536.f);
    float var = g_sumsq[0][c] * (1.f / 65536.f) - m * m;
    float rstd = 1.f / sqrtf(var + 1e-5f);
    float g1 = gamma[c] * rstd;
    float b1 = beta[c] - m * g1;
    g_g[0][c] = g1; g_b[0][c] = b1;
    float cmax = decf(g_cmax[c]), cmin = decf(g_cmin[c]);
    float hi = fmaxf(fmaxf(g1 * cmax + b1, g1 * cmin + b1), 0.f);
    __shared__ float red[256];
    red[c] = hi; __syncthreads();
    #pragma unroll
    for (int o = 128; o; o >>= 1) {
        if (c < o) red[c] = fmaxf(red[c], red[c + o]);
        __syncthreads();
    }
    if (c == 0) g_scale[3] = red[0] / 255.f + 1e-12f;
}

__global__ void k_finalize2(const float* __restrict__ gamma,
                            const float* __restrict__ beta) {
    int c = threadIdx.x;
    float m   = g_sum[1][c] * (1.f / 65536.f);
    float var = g_sumsq[1][c] * (1.f / 65536.f) - m * m;
    float rstd = 1.f / sqrtf(var + 1e-5f);
    float g2 = gamma[c] * rstd;
    g_g[1][c] = g2;
    g_b[1][c] = beta[c] - m * g2;
}

// ------ fused BN1 + ReLU + unsigned quant -> halo buffer (u-128 as s8) ----
__global__ void k_bn_quant() {
    __shared__ float sg[256], sb[256];
    if (threadIdx.x < 256) {
        sg[threadIdx.x] = g_g[0][threadIdx.x];
        sb[threadIdx.x] = g_b[0][threadIdx.x];
    }
    __syncthreads();
    float s = g_scale[3];
    int stride = gridDim.x * blockDim.x;
    for (int w = blockIdx.x * blockDim.x + threadIdx.x; w < NPIX * 64;
         w += stride) {
        float4 vv = ((const float4*)g_v)[w];
        int c = (w * 4) & 255;
        float r0 = fmaxf(sg[c]     * vv.x + sb[c],     0.f);
        float r1 = fmaxf(sg[c + 1] * vv.y + sb[c + 1], 0.f);
        float r2 = fmaxf(sg[c + 2] * vv.z + sb[c + 2], 0.f);
        float r3 = fmaxf(sg[c + 3] * vv.w + sb[c + 3], 0.f);
        int q0 = (int)fminf(fmaxf(rintf(r0 / s), 0.f), 255.f) - 128;
        int q1 = (int)fminf(fmaxf(rintf(r1 / s), 0.f), 255.f) - 128;
        int q2 = (int)fminf(fmaxf(rintf(r2 / s), 0.f), 255.f) - 128;
        int q3 = (int)fminf(fmaxf(rintf(r3 / s), 0.f), 255.f) - 128;
        uint32_t pk = (uint32_t)(q0 & 255) | ((uint32_t)(q1 & 255) << 8) |
                      ((uint32_t)(q2 & 255) << 16) | ((uint32_t)(q3 & 255) << 24);
        // halo layout dst
        int p  = w >> 6, cw = w & 63;
        int nn = p >> 10, rc = p & 1023;
        int r  = rc >> 5, cc = rc & 31;
        ((uint32_t*)(g_a8 + (size_t)nn * IMG_W))
            [((r + 1) * H2 + (cc + 1)) * 64 + cw] = pk;
    }
}

// ----------------- BN2 + residual + ReLU, NHWC -> NCHW transpose, write ---
__global__ void k_final(const float* __restrict__ x, float* __restrict__ out) {
    __shared__ float tile[32 * 257];
    int n   = blockIdx.x >> 5;
    int hw0 = (blockIdx.x & 31) * 32;
    int tid = threadIdx.x;
    float g2 = g_g[1][tid], b2 = g_b[1][tid];
    const float* v = g_v + (n * 1024 + hw0) * 256;
    for (int j = 0; j < 32; ++j)
        tile[j * 257 + tid] = g2 * v[j * 256 + tid] + b2;
    __syncthreads();
    for (int j = 0; j < 32; ++j) {
        int idx = j * 256 + tid;
        int c   = idx >> 5;
        int pix = idx & 31;
        int gi = ((n * 256 + c) << 10) + hw0 + pix;
        float r = tile[pix * 257 + c] + x[gi];
        out[gi] = fmaxf(r, 0.f);
    }
}

// ---------------------------------------------------------------------------
extern "C" void kernel_launch(void* const* d_in, const int* in_sizes, int n_in,
                              void* d_out, int out_size) {
    const float* x      = (const float*)d_in[0];
    const float* w1     = (const float*)d_in[1];
    const float* gamma1 = (const float*)d_in[2];
    const float* beta1  = (const float*)d_in[3];
    const float* w2     = (const float*)d_in[4];
    const float* gamma2 = (const float*)d_in[5];
    const float* beta2  = (const float*)d_in[6];
    float* out = (float*)d_out;

    dim3 cgrid(512, 2);
    k_init_halo<<<64, 256>>>();                        // 0: init + conv1 halo
    k_maxabs_all<<<1312, 256>>>((const float4*)x,      // 1
                                (const float4*)w1, (const float4*)w2);
    k_quant_x<<<2048, 256>>>(x);                       // 2
    k_quant_w_both<<<1024, 256>>>(w1, w2);             // 3
    k_wsum<<<256, 256>>>();                            // 4
    k_conv<false><<<cgrid, 256>>>(0);                  // 5  <- ncu captures this
    k_finalize1<<<1, 256>>>(gamma1, beta1);            // 6
    k_halo2<<<64, 256>>>();                            // 7: conv2 halo (u0)
    k_bn_quant<<<4096, 256>>>();                       // 8
    k_conv<true><<<cgrid, 256>>>(1);                   // 9
    k_finalize2<<<1, 256>>>(gamma2, beta2);            // 10
    k_final<<<2048, 256>>>(x, out);                    // 11
}

// round 17
// speedup vs baseline: 1.0269x; 1.0039x over previous
#include <cuda_runtime.h>
#include <cuda_bf16.h>
#include <cstdint>

// ---------------------------------------------------------------------------
// BasicBlock (quantized) exact-int8, IMMA convs, cp.async double-buffered.
//   acts int8 NHWC with 1-px halo: [64][34][34][256] (pad pre-filled)
//   conv = implicit GEMM, block 128 px x 128 oc, warp 32 px x 64 oc,
//          mma.m16n8k32.s8, 2-stage cp.async pipeline.
//   Launch order: conv1 at OUR index 3 = process ordinal 5 (harness emits
//   ~2 launches before ours; observed rounds 10 & 15 both captured index 3).
// ---------------------------------------------------------------------------

#define NPIX   65536          // 64*32*32
#define CCH    256
#define KTOT   2304           // 9*256
#define H2     34             // 32 + halo
#define IMG_W  (H2 * H2 * CCH)      // bytes per image (halo layout)

__device__ __align__(256) int8_t g_a8[64 * IMG_W];        // 18.9 MB halo acts
__device__ __align__(256) float  g_v [NPIX * CCH];        // 67 MB conv out
__device__ __align__(256) int8_t g_w1q[CCH * KTOT];
__device__ __align__(256) int8_t g_w2q[CCH * KTOT];
__device__ int      g_wsum2[CCH];
__device__ unsigned g_maxbits[4];        // |x|max, |w1|max, |w2|max
__device__ float    g_scale[4];          // [3] = unsigned act scale
__device__ float    g_sum[2][CCH], g_sumsq[2][CCH];
__device__ float    g_g[2][CCH], g_b[2][CCH];     // BN affine: g*v + b
__device__ unsigned g_cmin[CCH], g_cmax[CCH];     // conv1 per-channel extremes

// scale from raw nonneg float bits in g_maxbits (identical math everywhere)
__device__ __forceinline__ float mscale(int slot) {
    return __uint_as_float(g_maxbits[slot]) / 127.f + 1e-12f;
}

// monotone float<->uint encoding (order-preserving for atomicMin/Max)
__device__ __forceinline__ unsigned encf(float f) {
    unsigned b = __float_as_uint(f);
    return (b & 0x80000000u) ? ~b : (b | 0x80000000u);
}
__device__ __forceinline__ float decf(unsigned e) {
    unsigned b = (e & 0x80000000u) ? (e ^ 0x80000000u) : ~e;
    return __uint_as_float(b);
}

#define CP16(dst, src) \
    asm volatile("cp.async.cg.shared.global [%0], [%1], 16;" \
                 :: "r"(dst), "l"(src))

// --------------------------- init scalars + conv1 halo fill (one launch) ---
__global__ void k_init_halo() {
    int n = blockIdx.x;
    int tid = threadIdx.x;
    if (n == 0) {
        if (tid < 4) g_maxbits[tid] = 0u;
        g_sum[0][tid] = 0.f; g_sum[1][tid] = 0.f;
        g_sumsq[0][tid] = 0.f; g_sumsq[1][tid] = 0.f;
        g_cmin[tid] = 0xffffffffu; g_cmax[tid] = 0u;
        g_wsum2[tid] = 0;
    }
    uint32_t* img = (uint32_t*)(g_a8 + n * IMG_W);
    for (int w = tid; w < 132 * 64; w += blockDim.x) {
        int i = w >> 6, part = w & 63;
        int r, c;
        if (i < 34)       { r = 0;        c = i; }
        else if (i < 68)  { r = 33;       c = i - 34; }
        else if (i < 100) { r = i - 67;   c = 0; }    // rows 1..32
        else              { r = i - 99;   c = 33; }   // rows 1..32
        img[(r * H2 + c) * 64 + part] = 0u;
    }
}

// -------------------------------------------- halo fill (conv2, pad=0x80) ---
__global__ void k_halo2() {
    int n = blockIdx.x;
    uint32_t* img = (uint32_t*)(g_a8 + n * IMG_W);
    for (int w = threadIdx.x; w < 132 * 64; w += blockDim.x) {
        int i = w >> 6, part = w & 63;
        int r, c;
        if (i < 34)       { r = 0;        c = i; }
        else if (i < 68)  { r = 33;       c = i - 34; }
        else if (i < 100) { r = i - 67;   c = 0; }
        else              { r = i - 99;   c = 33; }
        img[(r * H2 + c) * 64 + part] = 0x80808080u;
    }
}

// ------------------------------- all three max|.| reductions, one launch ---
__global__ void k_maxabs_all(const float4* __restrict__ x,
                             const float4* __restrict__ w1,
                             const float4* __restrict__ w2) {
    int b = blockIdx.x;
    const float4* p; int n4, slot, b0, nb;
    if (b < 1184)      { p = x;  n4 = NPIX * 64;      slot = 0; b0 = b;        nb = 1184; }
    else if (b < 1248) { p = w1; n4 = CCH * KTOT / 4; slot = 1; b0 = b - 1184; nb = 64; }
    else               { p = w2; n4 = CCH * KTOT / 4; slot = 2; b0 = b - 1248; nb = 64; }
    float m = 0.f;
    for (int i = b0 * blockDim.x + threadIdx.x; i < n4; i += nb * blockDim.x) {
        float4 v = p[i];
        m = fmaxf(m, fmaxf(fmaxf(fabsf(v.x), fabsf(v.y)),
                           fmaxf(fabsf(v.z), fabsf(v.w))));
    }
    #pragma unroll
    for (int o = 16; o; o >>= 1) m = fmaxf(m, __shfl_xor_sync(~0u, m, o));
    if ((threadIdx.x & 31) == 0)
        atomicMax(&g_maxbits[slot], __float_as_uint(m));  // nonneg float bits
}

// ------------- quantize x (NCHW->halo NHWC s8) AND both weights, fused ----
// blocks [0,2048): x repack; blocks [2048,3072): weights.
__global__ void k_quant_all(const float* __restrict__ x,
                            const float* __restrict__ w1,
                            const float* __restrict__ w2) {
    __shared__ uint32_t tile32[32 * 66];
    if (blockIdx.x < 2048) {
        int8_t* tile = (int8_t*)tile32;
        int n = blockIdx.x >> 5;
        int r = blockIdx.x & 31;          // one full image row per block
        int hw0 = r * 32;
        int tid = threadIdx.x;
        float s = mscale(0);
        for (int j = 0; j < 32; ++j) {
            int idx = j * 256 + tid;
            int c   = idx >> 5;
            int pix = idx & 31;
            float v = x[((n * 256 + c) << 10) + hw0 + pix];
            float q = fminf(fmaxf(rintf(v / s), -128.f), 127.f);
            tile[pix * 264 + c] = (int8_t)q;
        }
        __syncthreads();
        uint32_t* dst = (uint32_t*)(g_a8 + n * IMG_W) + ((r + 1) * H2 + 1) * 64;
        for (int j = 0; j < 8; ++j) {
            int w   = j * 256 + tid;
            int pix = w >> 6;
            int cw  = w & 63;
            dst[pix * 64 + cw] = *(const uint32_t*)(tile + pix * 264 + cw * 4);
        }
    } else {
        int b = blockIdx.x - 2048;        // 0..1023
        int which = b >= 512;
        const float* w = which ? w2 : w1;
        int8_t* wq = which ? g_w2q : g_w1q;
        float s = mscale(which ? 2 : 1);
        int b0 = b & 511;
        for (int idx = b0 * blockDim.x + threadIdx.x; idx < CCH * KTOT;
             idx += 512 * blockDim.x) {
            int i = idx & 255;
            int t = (idx >> 8) % 9;
            int o = idx / KTOT;
            float v = w[(o * 256 + i) * 9 + t];
            float q = fminf(fmaxf(rintf(v / s), -128.f), 127.f);
            wq[idx] = (int8_t)q;
        }
    }
}

// per-out-channel sum of quantized w2 (unsigned zero-point trick)
__global__ void k_wsum() {
    int o = blockIdx.x, tid = threadIdx.x;
    int s = 0;
    #pragma unroll
    for (int t = 0; t < 9; ++t) s += (int)g_w2q[(o * 9 + t) * 256 + tid];
    #pragma unroll
    for (int off = 16; off; off >>= 1) s += __shfl_xor_sync(~0u, s, off);
    __shared__ int ws[8];
    if ((tid & 31) == 0) ws[tid >> 5] = s;
    __syncthreads();
    if (tid == 0) {
        int tot = 0;
        #pragma unroll
        for (int i = 0; i < 8; ++i) tot += ws[i];
        g_wsum2[o] = tot;
    }
}

// ------------------------------------------- conv3x3 as int8 IMMA GEMM ----
// grid = (512 pixel-tiles, 2 oc-tiles). Block tile = 128 px x 128 oc.
// 8 warps: (w&3) -> 32-px m-slice, (w>>2) -> 64-oc n-slice.
// 2-stage cp.async pipeline over 36 K-chunks (9 taps x 4 ic-chunks of 64B).
template <bool UNSIGNED>
__global__ void __launch_bounds__(256)
k_conv(int which) {
    // [buf][A=0/B=1][128 rows * 20 words]  = 40 KB static
    __shared__ __align__(16) uint32_t smemT[2][2][2560];
    const int8_t* Wq = which ? g_w2q : g_w1q;
    constexpr int STAGE = UNSIGNED ? 1 : 0;
    const int BUFB = 2 * 2560 * 4;            // bytes per pipeline stage

    int ptile = blockIdx.x;                   // 0..511
    int n  = ptile >> 3;
    int r4 = ptile & 7;                       // 4-row group
    int obase = blockIdx.y * 128;
    int tid = threadIdx.x;
    int warp = tid >> 5, lane = tid & 31;
    int m0 = (warp & 3) * 32;                 // pixel slice (32 px)
    int n0 = (warp >> 2) * 64;                // oc slice (64 oc)

    uint32_t smemBase = (uint32_t)__cvta_generic_to_shared(&smemT[0][0][0]);

    // ---- staging: thread = (spix 0..63, w0 0..3); ph=1 via const offsets --
    int spix = tid >> 2;
    int w0   = tid & 3;
    const int8_t* srcA = g_a8 + (size_t)n * IMG_W
                       + ((r4 * 4 + (spix >> 5) + 1) * H2 + (spix & 31) + 1) * 256
                       + w0 * 16;             // ph=1: +2 rows = +17408 B
    const int8_t* srcB = Wq + (size_t)(obase + spix) * KTOT + w0 * 16;  // ph=1: +64*KTOT
    uint32_t dstA0 = smemBase + (spix * 20 + w0 * 4) * 4;           // ph=1: +5120
    uint32_t dstB0 = smemBase + 10240 + (spix * 20 + w0 * 4) * 4;   // ph=1: +5120

    // ---- ldmatrix fragment addresses (relative; add buf*BUFB) ----
    uint32_t aAddr[2][2], bAddr0[4];
    #pragma unroll
    for (int mf = 0; mf < 2; ++mf)
        #pragma unroll
        for (int s = 0; s < 2; ++s)
            aAddr[mf][s] = smemBase + (m0 + mf * 16 + (lane & 15)) * 80
                         + (lane >> 4) * 16 + s * 32;
    #pragma unroll
    for (int j = 0; j < 4; ++j)
        bAddr0[j] = smemBase + 10240 + (n0 + j * 8 + (lane & 7)) * 80
                  + (lane >> 3) * 16;

    int acc[2][8][4] = {};

    // issue one 64B ic-chunk of one tap into stage `buf`
    auto issue = [&](int q, int buf) {
        int t = q >> 2, kc = q & 3;
        int tapoff = ((t / 3 - 1) * H2 + (t % 3 - 1)) * 256 + kc * 64;
        int boff = q * 64;                    // (t*256 + kc*64)
        uint32_t bo = (uint32_t)buf * BUFB;
        CP16(dstA0 + bo,        srcA + tapoff);
        CP16(dstB0 + bo,        srcB + boff);
        CP16(dstA0 + bo + 5120, srcA + tapoff + 2 * H2 * 256);
        CP16(dstB0 + bo + 5120, srcB + boff + 64 * KTOT);
        asm volatile("cp.async.commit_group;");
    };

    issue(0, 0);
    for (int q = 0; q < 36; ++q) {
        int buf = q & 1;
        if (q < 35) {
            issue(q + 1, buf ^ 1);
            asm volatile("cp.async.wait_group 1;");
        } else {
            asm volatile("cp.async.wait_group 0;");
        }
        __syncthreads();

        uint32_t bo = (uint32_t)buf * BUFB;
        uint32_t a[2][2][4];
        #pragma unroll
        for (int mf = 0; mf < 2; ++mf)
            #pragma unroll
            for (int s = 0; s < 2; ++s)
                asm volatile(
                    "ldmatrix.sync.aligned.m8n8.x4.shared.b16 {%0,%1,%2,%3}, [%4];"
                    : "=r"(a[mf][s][0]), "=r"(a[mf][s][1]),
                      "=r"(a[mf][s][2]), "=r"(a[mf][s][3])
                    : "r"(aAddr[mf][s] + bo));
        #pragma unroll
        for (int nh = 0; nh < 2; ++nh) {
            uint32_t b[4][4];
            #pragma unroll
            for (int j = 0; j < 4; ++j)
                asm volatile(
                    "ldmatrix.sync.aligned.m8n8.x4.shared.b16 {%0,%1,%2,%3}, [%4];"
                    : "=r"(b[j][0]), "=r"(b[j][1]), "=r"(b[j][2]), "=r"(b[j][3])
                    : "r"(bAddr0[j] + nh * 2560 + bo));
            #pragma unroll
            for (int mf = 0; mf < 2; ++mf)
                #pragma unroll
                for (int j = 0; j < 4; ++j)
                    #pragma unroll
                    for (int s = 0; s < 2; ++s)
                        asm volatile(
                            "mma.sync.aligned.m16n8k32.row.col.s32.s8.s8.s32 "
                            "{%0,%1,%2,%3}, {%4,%5,%6,%7}, {%8,%9}, {%0,%1,%2,%3};"
                            : "+r"(acc[mf][nh * 4 + j][0]),
                              "+r"(acc[mf][nh * 4 + j][1]),
                              "+r"(acc[mf][nh * 4 + j][2]),
                              "+r"(acc[mf][nh * 4 + j][3])
                            : "r"(a[mf][s][0]), "r"(a[mf][s][1]),
                              "r"(a[mf][s][2]), "r"(a[mf][s][3]),
                              "r"(b[j][2 * s]), "r"(b[j][2 * s + 1]));
        }
        __syncthreads();                      // protect buf before reuse
    }

    // ------------------------------ epilogue: write f32 + fused BN stats ---
    float s = UNSIGNED ? g_scale[3] * mscale(2) : mscale(0) * mscale(1);
    int groupID = lane >> 2, tig = lane & 3;

    #pragma unroll
    for (int j8 = 0; j8 < 8; ++j8) {
        int oc = obase + n0 + j8 * 8 + tig * 2;
        int wsa = 0, wsb = 0;
        if (UNSIGNED) { wsa = 128 * g_wsum2[oc]; wsb = 128 * g_wsum2[oc + 1]; }
        float sx = 0.f, sy = 0.f, qx = 0.f, qy = 0.f;
        float mnx = 1e30f, mxx = -1e30f, mny = 1e30f, mxy = -1e30f;
        #pragma unroll
        for (int mf = 0; mf < 2; ++mf) {
            int pix0 = m0 + mf * 16 + groupID;        // tile-local 0..127
            #pragma unroll
            for (int half = 0; half < 2; ++half) {
                int pix = pix0 + half * 8;
                int gp = n * 1024 + (r4 * 4 + (pix >> 5)) * 32 + (pix & 31);
                int c0 = acc[mf][j8][half * 2]     + wsa;
                int c1 = acc[mf][j8][half * 2 + 1] + wsb;
                float va = s * (float)c0, vb = s * (float)c1;
                *(float2*)(g_v + gp * 256 + oc) = make_float2(va, vb);
                sx += va; sy += vb;
                qx += va * va; qy += vb * vb;
                if (!UNSIGNED) {
                    mnx = fminf(mnx, va); mxx = fmaxf(mxx, va);
                    mny = fminf(mny, vb); mxy = fmaxf(mxy, vb);
                }
            }
        }
        #pragma unroll
        for (int o = 4; o < 32; o <<= 1) {    // reduce across the 8 groupIDs
            sx += __shfl_xor_sync(~0u, sx, o);
            sy += __shfl_xor_sync(~0u, sy, o);
            qx += __shfl_xor_sync(~0u, qx, o);
            qy += __shfl_xor_sync(~0u, qy, o);
            if (!UNSIGNED) {
                mnx = fminf(mnx, __shfl_xor_sync(~0u, mnx, o));
                mxx = fmaxf(mxx, __shfl_xor_sync(~0u, mxx, o));
                mny = fminf(mny, __shfl_xor_sync(~0u, mny, o));
                mxy = fmaxf(mxy, __shfl_xor_sync(~0u, mxy, o));
            }
        }
        if (groupID == 0) {
            atomicAdd(&g_sum[STAGE][oc],       sx);
            atomicAdd(&g_sum[STAGE][oc + 1],   sy);
            atomicAdd(&g_sumsq[STAGE][oc],     qx);
            atomicAdd(&g_sumsq[STAGE][oc + 1], qy);
            if (!UNSIGNED) {
                atomicMin(&g_cmin[oc],     encf(mnx));
                atomicMax(&g_cmax[oc],     encf(mxx));
                atomicMin(&g_cmin[oc + 1], encf(mny));
                atomicMax(&g_cmax[oc + 1], encf(mxy));
            }
        }
    }
}

// -------- finalize BN1: affine coeffs + analytic ReLU-max -> u8 scale ----
__global__ void k_finalize1(const float* __restrict__ gamma,
                            const float* __restrict__ beta) {
    int c = threadIdx.x;
    float m   = g_sum[0][c] * (1.f / 65536.f);
    float var = g_sumsq[0][c] * (1.f / 65536.f) - m * m;
    float rstd = 1.f / sqrtf(var + 1e-5f);
    float g1 = gamma[c] * rstd;
    float b1 = beta[c] - m * g1;
    g_g[0][c] = g1; g_b[0][c] = b1;
    float cmax = decf(g_cmax[c]), cmin = decf(g_cmin[c]);
    float hi = fmaxf(fmaxf(g1 * cmax + b1, g1 * cmin + b1), 0.f);
    __shared__ float red[256];
    red[c] = hi; __syncthreads();
    #pragma unroll
    for (int o = 128; o; o >>= 1) {
        if (c < o) red[c] = fmaxf(red[c], red[c + o]);
        __syncthreads();
    }
    if (c == 0) g_scale[3] = red[0] / 255.f + 1e-12f;
}

__global__ void k_finalize2(const float* __restrict__ gamma,
                            const float* __restrict__ beta) {
    int c = threadIdx.x;
    float m   = g_sum[1][c] * (1.f / 65536.f);
    float var = g_sumsq[1][c] * (1.f / 65536.f) - m * m;
    float rstd = 1.f / sqrtf(var + 1e-5f);
    float g2 = gamma[c] * rstd;
    g_g[1][c] = g2;
    g_b[1][c] = beta[c] - m * g2;
}

// ------ fused BN1 + ReLU + unsigned quant -> halo buffer (u-128 as s8) ----
__global__ void k_bn_quant() {
    __shared__ float sg[256], sb[256];
    if (threadIdx.x < 256) {
        sg[threadIdx.x] = g_g[0][threadIdx.x];
        sb[threadIdx.x] = g_b[0][threadIdx.x];
    }
    __syncthreads();
    float s = g_scale[3];
    int stride = gridDim.x * blockDim.x;
    for (int w = blockIdx.x * blockDim.x + threadIdx.x; w < NPIX * 64;
         w += stride) {
        float4 vv = ((const float4*)g_v)[w];
        int c = (w * 4) & 255;
        float r0 = fmaxf(sg[c]     * vv.x + sb[c],     0.f);
        float r1 = fmaxf(sg[c + 1] * vv.y + sb[c + 1], 0.f);
        float r2 = fmaxf(sg[c + 2] * vv.z + sb[c + 2], 0.f);
        float r3 = fmaxf(sg[c + 3] * vv.w + sb[c + 3], 0.f);
        int q0 = (int)fminf(fmaxf(rintf(r0 / s), 0.f), 255.f) - 128;
        int q1 = (int)fminf(fmaxf(rintf(r1 / s), 0.f), 255.f) - 128;
        int q2 = (int)fminf(fmaxf(rintf(r2 / s), 0.f), 255.f) - 128;
        int q3 = (int)fminf(fmaxf(rintf(r3 / s), 0.f), 255.f) - 128;
        uint32_t pk = (uint32_t)(q0 & 255) | ((uint32_t)(q1 & 255) << 8) |
                      ((uint32_t)(q2 & 255) << 16) | ((uint32_t)(q3 & 255) << 24);
        // halo layout dst
        int p  = w >> 6, cw = w & 63;
        int nn = p >> 10, rc = p & 1023;
        int r  = rc >> 5, cc = rc & 31;
        ((uint32_t*)(g_a8 + (size_t)nn * IMG_W))
            [((r + 1) * H2 + (cc + 1)) * 64 + cw] = pk;
    }
}

// ----------------- BN2 + residual + ReLU, NHWC -> NCHW transpose, write ---
__global__ void k_final(const float* __restrict__ x, float* __restrict__ out) {
    __shared__ float tile[32 * 257];
    int n   = blockIdx.x >> 5;
    int hw0 = (blockIdx.x & 31) * 32;
    int tid = threadIdx.x;
    float g2 = g_g[1][tid], b2 = g_b[1][tid];
    const float* v = g_v + (n * 1024 + hw0) * 256;
    for (int j = 0; j < 32; ++j)
        tile[j * 257 + tid] = g2 * v[j * 256 + tid] + b2;
    __syncthreads();
    for (int j = 0; j < 32; ++j) {
        int idx = j * 256 + tid;
        int c   = idx >> 5;
        int pix = idx & 31;
        int gi = ((n * 256 + c) << 10) + hw0 + pix;
        float r = tile[pix * 257 + c] + x[gi];
        out[gi] = fmaxf(r, 0.f);
    }
}

// ---------------------------------------------------------------------------
extern "C" void kernel_launch(void* const* d_in, const int* in_sizes, int n_in,
                              void* d_out, int out_size) {
    const float* x      = (const float*)d_in[0];
    const float* w1     = (const float*)d_in[1];
    const float* gamma1 = (const float*)d_in[2];
    const float* beta1  = (const float*)d_in[3];
    const float* w2     = (const float*)d_in[4];
    const float* gamma2 = (const float*)d_in[5];
    const float* beta2  = (const float*)d_in[6];
    float* out = (float*)d_out;

    dim3 cgrid(512, 2);
    k_init_halo<<<64, 256>>>();                        // 0: init + conv1 halo
    k_maxabs_all<<<1312, 256>>>((const float4*)x,      // 1
                                (const float4*)w1, (const float4*)w2);
    k_quant_all<<<3072, 256>>>(x, w1, w2);             // 2: x + both weights
    k_conv<false><<<cgrid, 256>>>(0);                  // 3  <- process ordinal 5
    k_wsum<<<256, 256>>>();                            // 4 (needed by conv2 only)
    k_finalize1<<<1, 256>>>(gamma1, beta1);            // 5
    k_halo2<<<64, 256>>>();                            // 6: conv2 halo (u0)
    k_bn_quant<<<4096, 256>>>();                       // 7
    k_conv<true><<<cgrid, 256>>>(1);                   // 8
    k_finalize2<<<1, 256>>>(gamma2, beta2);            // 9
    k_final<<<2048, 256>>>(x, out);                    // 10
}